// round 12
// baseline (speedup 1.0000x reference)
#include <cuda_runtime.h>
#include <cuda_fp16.h>
#include <stdint.h>
#include <math.h>

#define NEXP 8
#define BTOK 4096
#define DIN  1024
#define DHID 4096
#define DOUT 1024

// fp16 activation planes (device globals; no allocation inside kernel_launch)
__device__ __half g_xq[(size_t)BTOK * DIN];
__device__ __half g_hq[(size_t)BTOK * DHID];
__device__ int g_counts[NEXP], g_offsets[NEXP], g_order[BTOK];

// ---------------------------------------------------------------------------
// Helpers
// ---------------------------------------------------------------------------
__device__ __forceinline__ uint32_t smem_u32(const void* p) {
    uint32_t a;
    asm("{ .reg .u64 t; cvta.to.shared.u64 t, %1; cvt.u32.u64 %0, t; }"
        : "=r"(a) : "l"(p));
    return a;
}

__device__ __forceinline__ void ldm_x4(uint32_t* r, uint32_t addr) {
    asm volatile("ldmatrix.sync.aligned.m8n8.x4.shared.b16 {%0,%1,%2,%3}, [%4];"
                 : "=r"(r[0]), "=r"(r[1]), "=r"(r[2]), "=r"(r[3]) : "r"(addr));
}
__device__ __forceinline__ void ldm_x4_t(uint32_t* r, uint32_t addr) {
    asm volatile("ldmatrix.sync.aligned.m8n8.x4.trans.shared.b16 {%0,%1,%2,%3}, [%4];"
                 : "=r"(r[0]), "=r"(r[1]), "=r"(r[2]), "=r"(r[3]) : "r"(addr));
}

__device__ __forceinline__ void mma_f16(float* d, const uint32_t* a,
                                        uint32_t b0, uint32_t b1) {
    asm volatile(
        "mma.sync.aligned.m16n8k16.row.col.f32.f16.f16.f32 "
        "{%0,%1,%2,%3}, {%4,%5,%6,%7}, {%8,%9}, {%0,%1,%2,%3};"
        : "+f"(d[0]), "+f"(d[1]), "+f"(d[2]), "+f"(d[3])
        : "r"(a[0]), "r"(a[1]), "r"(a[2]), "r"(a[3]), "r"(b0), "r"(b1));
}

#define CP16(dst, src) \
    asm volatile("cp.async.cg.shared.global [%0], [%1], 16;" \
                 :: "r"(dst), "l"(src) : "memory")
#define CP_COMMIT() asm volatile("cp.async.commit_group;" ::: "memory")
#define CP_WAIT(n)  asm volatile("cp.async.wait_group %0;" :: "n"(n) : "memory")

__device__ __forceinline__ void sts64(uint32_t addr, uint32_t v0, uint32_t v1) {
    asm volatile("st.shared.v2.b32 [%0], {%1, %2};"
                 :: "r"(addr), "r"(v0), "r"(v1) : "memory");
}

__device__ __forceinline__ float gelu_tanh(float x) {
    float x3 = x * x * x;
    return 0.5f * x * (1.0f + tanhf(0.7978845608028654f * (x + 0.044715f * x3)));
}

__device__ __forceinline__ uint32_t pack_h2(float a, float b) {
    __half2 t(__float2half_rn(a), __float2half_rn(b));
    return *reinterpret_cast<uint32_t*>(&t);
}

// ---------------------------------------------------------------------------
// Routing (single block): dtype-detect, count, scan, scatter
// ---------------------------------------------------------------------------
__global__ __launch_bounds__(1024)
void route_kernel(const int* __restrict__ r32) {
    __shared__ int s32, scnt[NEXP], soff[NEXP];
    int tid = threadIdx.x;
    if (tid == 0) s32 = 0;
    if (tid < NEXP) scnt[tid] = 0;
    __syncthreads();
    // int64 route: every odd int32 word of the first 4096 is a zero hi-half.
    int f = 0;
    for (int i = tid * 2 + 1; i < BTOK; i += 2048) f |= r32[i];
    if (f) atomicOr(&s32, 1);
    __syncthreads();
    bool is32 = (s32 != 0);
    int mym[4], myrank[4];
    #pragma unroll
    for (int j = 0; j < 4; j++) {
        int b = tid + j * 1024;
        int m = is32 ? r32[b] : (int)((const long long*)r32)[b];
        mym[j] = m;
        myrank[j] = atomicAdd(&scnt[m], 1);
    }
    __syncthreads();
    if (tid == 0) {
        int s = 0;
        for (int m = 0; m < NEXP; m++) {
            soff[m] = s; g_offsets[m] = s; g_counts[m] = scnt[m]; s += scnt[m];
        }
    }
    __syncthreads();
    #pragma unroll
    for (int j = 0; j < 4; j++)
        g_order[soff[mym[j]] + myrank[j]] = tid + j * 1024;
}

// ---------------------------------------------------------------------------
// Quantize x: fp32 -> fp16, same layout. 8 elems/thread.
// ---------------------------------------------------------------------------
__global__ __launch_bounds__(256)
void quant_x_kernel(const float* __restrict__ x) {
    int i = blockIdx.x * 256 + threadIdx.x;
    float4 v0 = reinterpret_cast<const float4*>(x)[2 * i];
    float4 v1 = reinterpret_cast<const float4*>(x)[2 * i + 1];
    uint4 o;
    o.x = pack_h2(v0.x, v0.y); o.y = pack_h2(v0.z, v0.w);
    o.z = pack_h2(v1.x, v1.y); o.w = pack_h2(v1.z, v1.w);
    reinterpret_cast<uint4*>(g_xq)[i] = o;
}

// ---------------------------------------------------------------------------
// Grouped GEMM: HMMA m16n8k16 fp16, fp32 acc, single pass.
// CTA 128x128, K-chunk 64, 8 warps (4m x 2n), warp tile 32x64.
// TWO CTAs per SM (__launch_bounds__(256,2)) — independent barriers
// interleave and keep the legacy HMMA pipe fed (R3-proven pattern).
// A: fp16 plane, 4-stage cp.async (128 rows x 128B, XOR-swizzled).
// B: fused conversion — W fp32 [m][K][N] loaded per-chunk (coalesced f4
//    along N), cvt fp16 in regs, STS into k-major tile (64 rows x 272B
//    padded stride = conflict-free trans ldmatrix), 2 stages.
// Single barrier per chunk (R9/R11-proven safety argument).
// ---------------------------------------------------------------------------
static constexpr int A_STAGE   = 16384;                 // 128 x 128B
static constexpr int A_TOTAL   = 4 * A_STAGE;           // 65536
static constexpr int B_ROW     = 272;                   // 256B + 16B pad
static constexpr int B_STAGE   = 64 * B_ROW;            // 17408
static constexpr int SMEM_DYN  = A_TOTAL + 2 * B_STAGE; // 100352 (x2 <= SM)

template <int K, int NTOT, bool LAYER1>
__global__ __launch_bounds__(256, 2)
void moe_gemm(const __half* __restrict__ Aq, const float* __restrict__ W,
              const float* __restrict__ bias, float* __restrict__ Cout)
{
    const int m    = blockIdx.z;
    const int cnt  = g_counts[m];
    const int row0 = blockIdx.y * 128;
    if (row0 >= cnt) return;
    const int goff = g_offsets[m];
    const int n0   = blockIdx.x * 128;
    const int tid  = threadIdx.x;
    const int wid  = tid >> 5;
    const int lane = tid & 31;
    const int wm   = wid & 3;          // warp row block (32 rows)
    const int wn   = wid >> 2;         // warp col block (64 cols), 0..1

    extern __shared__ char smem_raw[];
    const uint32_t sbase = smem_u32(smem_raw);
    const uint32_t bbase = sbase + A_TOTAL;

    // ---- A cp.async mapping: tid<128 -> A row tid (8 x 16B per chunk)
    const bool isA = (tid < 128);
    const int  arow = tid & 127;
    const __half* asrc = nullptr;
    if (isA) {
        int grow = row0 + arow;
        int gr   = (grow < cnt) ? (goff + grow) : goff;   // clamp (cnt >= 1)
        asrc = (LAYER1 ? Aq + (size_t)g_order[gr] * K
                       : Aq + (size_t)gr * K);
    }
    const uint32_t aswz = (uint32_t)((arow ^ (arow >> 3)) & 7);
    const uint32_t adof = (uint32_t)arow * 128u;

    // ---- B fused-conversion mapping: 256 threads, 8 float4 per chunk
    // idx = tid + j*256 over 64 k-rows x 32 f4-cols
    const float* wsrc = W + (size_t)m * K * NTOT + n0;
    // per-j: k = idx>>5, c4 = idx&31; STS dest: k*272 + c4*8

    // ---- ldmatrix address precompute ----
    const uint32_t uh = lane >> 4;          // 16B unit within k16 (A)
    uint32_t a_off[2], a_swz[2];
    #pragma unroll
    for (int mt = 0; mt < 2; mt++) {
        int r = wm * 32 + mt * 16 + (lane & 15);
        a_off[mt] = (uint32_t)r * 128u;
        a_swz[mt] = (uint32_t)((r ^ (r >> 3)) & 7);
    }
    // B trans frag: k-row = ks*16 + (lane&15); col = wn*64 + ng*16 + (lane>>4)*8
    const uint32_t b_ldm = (uint32_t)((lane & 15) * B_ROW
                         + (wn * 64 + (lane >> 4) * 8) * 2);

    float acc[2][8][4] = {};
    const int NCH = K / 64;

    // ---- prologue ----
    // B chunk 0 -> b-stage 0
    {
        float4 bv[8];
        #pragma unroll
        for (int j = 0; j < 8; j++) {
            int idx = tid + j * 256;
            bv[j] = *reinterpret_cast<const float4*>(
                wsrc + (size_t)(idx >> 5) * NTOT + (idx & 31) * 4);
        }
        #pragma unroll
        for (int j = 0; j < 8; j++) {
            int idx = tid + j * 256;
            sts64(bbase + (uint32_t)((idx >> 5) * B_ROW + (idx & 31) * 8),
                  pack_h2(bv[j].x, bv[j].y), pack_h2(bv[j].z, bv[j].w));
        }
    }
    // A stages 0,1,2
    #pragma unroll
    for (int s = 0; s < 3; s++) {
        if (isA) {
            const __half* sp = asrc + s * 64;
            const uint32_t stp = sbase + s * A_STAGE;
            #pragma unroll
            for (int u = 0; u < 8; u++)
                CP16(stp + adof + (((u ^ aswz) & 7) << 4), sp + u * 8);
        }
        CP_COMMIT();
    }

    for (int c = 0; c < NCH; c++) {
        if      (c + 3 <= NCH) { CP_WAIT(2); }
        else if (c + 2 <= NCH) { CP_WAIT(1); }
        else                   { CP_WAIT(0); }
        __syncthreads();   // single barrier per chunk

        // A prefetch chunk c+3
        if (c + 3 < NCH) {
            const uint32_t st2 = sbase + ((c + 3) & 3) * A_STAGE;
            if (isA) {
                const __half* s2 = asrc + (c + 3) * 64;
                #pragma unroll
                for (int u = 0; u < 8; u++)
                    CP16(st2 + adof + (((u ^ aswz) & 7) << 4), s2 + u * 8);
            }
            CP_COMMIT();
        }

        // B prefetch chunk c+1 into registers (STS after MMA)
        float4 bv[8];
        if (c + 1 < NCH) {
            const float* w2 = wsrc + (size_t)(c + 1) * 64 * NTOT;
            #pragma unroll
            for (int j = 0; j < 8; j++) {
                int idx = tid + j * 256;
                bv[j] = *reinterpret_cast<const float4*>(
                    w2 + (size_t)(idx >> 5) * NTOT + (idx & 31) * 4);
            }
        }

        // ---- MMA on chunk c: A stage c&3, B stage c&1 ----
        const uint32_t ast = sbase + (c & 3) * A_STAGE;
        const uint32_t bst = bbase + (c & 1) * B_STAGE;
        #pragma unroll
        for (int ks = 0; ks < 4; ks++) {
            const uint32_t u = ks * 2 + uh;
            uint32_t a[2][4];
            #pragma unroll
            for (int mt = 0; mt < 2; mt++)
                ldm_x4(a[mt], ast + a_off[mt] + (((u ^ a_swz[mt]) & 7) << 4));
            #pragma unroll
            for (int ng = 0; ng < 4; ng++) {
                uint32_t b[4];
                ldm_x4_t(b, bst + b_ldm + ks * 16 * B_ROW + ng * 32);
                #pragma unroll
                for (int mt = 0; mt < 2; mt++) {
                    mma_f16(acc[mt][ng * 2 + 0], a[mt], b[0], b[1]);
                    mma_f16(acc[mt][ng * 2 + 1], a[mt], b[2], b[3]);
                }
            }
        }

        // STS B chunk c+1 into stage (c+1)&1
        if (c + 1 < NCH) {
            const uint32_t bs2 = bbase + ((c + 1) & 1) * B_STAGE;
            #pragma unroll
            for (int j = 0; j < 8; j++) {
                int idx = tid + j * 256;
                sts64(bs2 + (uint32_t)((idx >> 5) * B_ROW + (idx & 31) * 8),
                      pack_h2(bv[j].x, bv[j].y), pack_h2(bv[j].z, bv[j].w));
            }
        }
    }

    // ---- Epilogue ----
    const float* bp = bias + (size_t)m * NTOT + n0;
    #pragma unroll
    for (int mt = 0; mt < 2; mt++) {
        #pragma unroll
        for (int half = 0; half < 2; half++) {
            int rloc = wm * 32 + mt * 16 + (lane >> 2) + half * 8;
            int r = row0 + rloc;
            if (r >= cnt) continue;
            if (LAYER1) {
                __half* hp = g_hq + (size_t)(goff + r) * NTOT + n0;
                #pragma unroll
                for (int nt = 0; nt < 8; nt++) {
                    int col = wn * 64 + nt * 8 + (lane & 3) * 2;
                    float v0 = gelu_tanh(acc[mt][nt][half * 2 + 0] + bp[col]);
                    float v1 = gelu_tanh(acc[mt][nt][half * 2 + 1] + bp[col + 1]);
                    *reinterpret_cast<uint32_t*>(hp + col) = pack_h2(v0, v1);
                }
            } else {
                float* cp = Cout + (size_t)g_order[goff + r] * NTOT + n0;
                #pragma unroll
                for (int nt = 0; nt < 8; nt++) {
                    int col = wn * 64 + nt * 8 + (lane & 3) * 2;
                    float2 v;
                    v.x = acc[mt][nt][half * 2 + 0] + bp[col];
                    v.y = acc[mt][nt][half * 2 + 1] + bp[col + 1];
                    *reinterpret_cast<float2*>(cp + col) = v;
                }
            }
        }
    }
}

// ---------------------------------------------------------------------------
extern "C" void kernel_launch(void* const* d_in, const int* in_sizes, int n_in,
                              void* d_out, int out_size)
{
    const float* x     = (const float*)d_in[0];
    const void*  route = d_in[1];
    const float* W1    = (const float*)d_in[2];
    const float* b1    = (const float*)d_in[3];
    const float* W2    = (const float*)d_in[4];
    const float* b2    = (const float*)d_in[5];
    float*       out   = (float*)d_out;

    __half *xq, *hq;
    cudaGetSymbolAddress((void**)&xq, g_xq);
    cudaGetSymbolAddress((void**)&hq, g_hq);

    cudaFuncSetAttribute(moe_gemm<DIN, DHID, true>,
                         cudaFuncAttributeMaxDynamicSharedMemorySize, SMEM_DYN);
    cudaFuncSetAttribute(moe_gemm<DHID, DOUT, false>,
                         cudaFuncAttributeMaxDynamicSharedMemorySize, SMEM_DYN);

    route_kernel<<<1, 1024>>>((const int*)route);
    quant_x_kernel<<<(BTOK * DIN / 8) / 256, 256>>>(x);

    {   // Layer 1: g_hq = fp16(gelu(x @ W1[m] + b1[m])), grouped by expert
        dim3 g(DHID / 128, BTOK / 128, NEXP);
        moe_gemm<DIN, DHID, true><<<g, 256, SMEM_DYN>>>(xq, W1, b1, nullptr);
    }
    {   // Layer 2: out[tok] = h @ W2[m] + b2[m]
        dim3 g(DOUT / 128, BTOK / 128, NEXP);
        moe_gemm<DHID, DOUT, false><<<g, 256, SMEM_DYN>>>(hq, W2, b2, out);
    }
}

// round 13
// speedup vs baseline: 1.4067x; 1.4067x over previous
#include <cuda_runtime.h>
#include <cuda_fp16.h>
#include <stdint.h>
#include <math.h>

#define NEXP 8
#define BTOK 4096
#define DIN  1024
#define DHID 4096
#define DOUT 1024
#define MAXTILES 40   // sum ceil(cnt_m/128) <= BTOK/128 + NEXP = 40

// fp16 activation planes (device globals; no allocation inside kernel_launch)
__device__ __half g_xq[(size_t)BTOK * DIN];
__device__ __half g_hq[(size_t)BTOK * DHID];
__device__ int g_counts[NEXP], g_offsets[NEXP], g_order[BTOK];
__device__ int g_tiles[MAXTILES];   // packed (m << 16) | row_tile_index
__device__ int g_ntiles;

// ---------------------------------------------------------------------------
// Helpers
// ---------------------------------------------------------------------------
__device__ __forceinline__ uint32_t smem_u32(const void* p) {
    uint32_t a;
    asm("{ .reg .u64 t; cvta.to.shared.u64 t, %1; cvt.u32.u64 %0, t; }"
        : "=r"(a) : "l"(p));
    return a;
}

__device__ __forceinline__ void ldm_x4(uint32_t* r, uint32_t addr) {
    asm volatile("ldmatrix.sync.aligned.m8n8.x4.shared.b16 {%0,%1,%2,%3}, [%4];"
                 : "=r"(r[0]), "=r"(r[1]), "=r"(r[2]), "=r"(r[3]) : "r"(addr));
}
__device__ __forceinline__ void ldm_x4_t(uint32_t* r, uint32_t addr) {
    asm volatile("ldmatrix.sync.aligned.m8n8.x4.trans.shared.b16 {%0,%1,%2,%3}, [%4];"
                 : "=r"(r[0]), "=r"(r[1]), "=r"(r[2]), "=r"(r[3]) : "r"(addr));
}

__device__ __forceinline__ void mma_f16(float* d, const uint32_t* a,
                                        uint32_t b0, uint32_t b1) {
    asm volatile(
        "mma.sync.aligned.m16n8k16.row.col.f32.f16.f16.f32 "
        "{%0,%1,%2,%3}, {%4,%5,%6,%7}, {%8,%9}, {%0,%1,%2,%3};"
        : "+f"(d[0]), "+f"(d[1]), "+f"(d[2]), "+f"(d[3])
        : "r"(a[0]), "r"(a[1]), "r"(a[2]), "r"(a[3]), "r"(b0), "r"(b1));
}

#define CP16(dst, src) \
    asm volatile("cp.async.cg.shared.global [%0], [%1], 16;" \
                 :: "r"(dst), "l"(src) : "memory")
#define CP_COMMIT() asm volatile("cp.async.commit_group;" ::: "memory")
#define CP_WAIT(n)  asm volatile("cp.async.wait_group %0;" :: "n"(n) : "memory")

__device__ __forceinline__ void sts64(uint32_t addr, uint32_t v0, uint32_t v1) {
    asm volatile("st.shared.v2.b32 [%0], {%1, %2};"
                 :: "r"(addr), "r"(v0), "r"(v1) : "memory");
}

__device__ __forceinline__ float gelu_tanh(float x) {
    float x3 = x * x * x;
    return 0.5f * x * (1.0f + tanhf(0.7978845608028654f * (x + 0.044715f * x3)));
}

__device__ __forceinline__ uint32_t pack_h2(float a, float b) {
    __half2 t(__float2half_rn(a), __float2half_rn(b));
    return *reinterpret_cast<uint32_t*>(&t);
}

// ---------------------------------------------------------------------------
// Routing (single block): dtype-detect, count, scan, scatter + tile table
// ---------------------------------------------------------------------------
__global__ __launch_bounds__(1024)
void route_kernel(const int* __restrict__ r32) {
    __shared__ int s32, scnt[NEXP], soff[NEXP];
    int tid = threadIdx.x;
    if (tid == 0) s32 = 0;
    if (tid < NEXP) scnt[tid] = 0;
    __syncthreads();
    // int64 route: every odd int32 word of the first 4096 is a zero hi-half.
    int f = 0;
    for (int i = tid * 2 + 1; i < BTOK; i += 2048) f |= r32[i];
    if (f) atomicOr(&s32, 1);
    __syncthreads();
    bool is32 = (s32 != 0);
    int mym[4], myrank[4];
    #pragma unroll
    for (int j = 0; j < 4; j++) {
        int b = tid + j * 1024;
        int m = is32 ? r32[b] : (int)((const long long*)r32)[b];
        mym[j] = m;
        myrank[j] = atomicAdd(&scnt[m], 1);
    }
    __syncthreads();
    if (tid == 0) {
        int s = 0, t = 0;
        for (int m = 0; m < NEXP; m++) {
            soff[m] = s; g_offsets[m] = s; g_counts[m] = scnt[m]; s += scnt[m];
            for (int rt = 0; rt * 128 < scnt[m]; rt++)
                g_tiles[t++] = (m << 16) | rt;
        }
        g_ntiles = t;
    }
    __syncthreads();
    #pragma unroll
    for (int j = 0; j < 4; j++)
        g_order[soff[mym[j]] + myrank[j]] = tid + j * 1024;
}

// ---------------------------------------------------------------------------
// Quantize x: fp32 -> fp16, same layout. 8 elems/thread.
// ---------------------------------------------------------------------------
__global__ __launch_bounds__(256)
void quant_x_kernel(const float* __restrict__ x) {
    int i = blockIdx.x * 256 + threadIdx.x;
    float4 v0 = reinterpret_cast<const float4*>(x)[2 * i];
    float4 v1 = reinterpret_cast<const float4*>(x)[2 * i + 1];
    uint4 o;
    o.x = pack_h2(v0.x, v0.y); o.y = pack_h2(v0.z, v0.w);
    o.z = pack_h2(v1.x, v1.y); o.w = pack_h2(v1.z, v1.w);
    reinterpret_cast<uint4*>(g_xq)[i] = o;
}

// ---------------------------------------------------------------------------
// Grouped GEMM: HMMA m16n8k16 fp16, fp32 acc, single pass. (R11 mainloop)
// CTA 128x256, K-chunk 64, 16 warps (4m x 4n), warp tile 32x64.
// Work-list grid: blockIdx.y indexes g_tiles (no empty-CTA waste).
// A: fp16 plane, 4-stage cp.async (128 rows x 128B, XOR-swizzled).
// B: fused conversion — W fp32 [m][K][N] loaded per-chunk, cvt fp16 in regs,
//    STS into k-major tile (64 rows x 528B, conflict-free), 2 stages.
// Single barrier per chunk.
// ---------------------------------------------------------------------------
static constexpr int A_STAGE   = 16384;                 // 128 x 128B
static constexpr int A_TOTAL   = 4 * A_STAGE;           // 65536
static constexpr int B_ROW     = 528;                   // 512B + 16B pad
static constexpr int B_STAGE   = 64 * B_ROW;            // 33792
static constexpr int SMEM_DYN  = A_TOTAL + 2 * B_STAGE; // 133120

template <int K, int NTOT, bool LAYER1>
__global__ __launch_bounds__(512, 1)
void moe_gemm(const __half* __restrict__ Aq, const float* __restrict__ W,
              const float* __restrict__ bias, float* __restrict__ Cout)
{
    if (blockIdx.y >= (unsigned)g_ntiles) return;
    const int pack = g_tiles[blockIdx.y];
    const int m    = pack >> 16;
    const int row0 = (pack & 0xFFFF) * 128;
    const int cnt  = g_counts[m];
    const int goff = g_offsets[m];
    const int n0   = blockIdx.x * 256;
    const int tid  = threadIdx.x;
    const int wid  = tid >> 5;
    const int lane = tid & 31;
    const int wm   = wid & 3;          // warp row block (32 rows)
    const int wn   = wid >> 2;         // warp col block (64 cols), 0..3

    extern __shared__ char smem_raw[];
    const uint32_t sbase = smem_u32(smem_raw);
    const uint32_t bbase = sbase + A_TOTAL;

    // ---- A cp.async mapping: tid<128 -> A row tid (8 x 16B per chunk)
    const bool isA = (tid < 128);
    const int  arow = tid & 127;
    const __half* asrc = nullptr;
    if (isA) {
        int grow = row0 + arow;
        int gr   = (grow < cnt) ? (goff + grow) : goff;   // clamp (cnt >= 1)
        asrc = (LAYER1 ? Aq + (size_t)g_order[gr] * K
                       : Aq + (size_t)gr * K);
    }
    const uint32_t aswz = (uint32_t)((arow ^ (arow >> 3)) & 7);
    const uint32_t adof = (uint32_t)arow * 128u;

    // ---- B fused-conversion mapping: 512 threads, 8 float4 per chunk
    const float* wsrc = W + (size_t)m * K * NTOT + n0;

    // ---- ldmatrix address precompute ----
    const uint32_t uh = lane >> 4;          // 16B unit within k16 (A)
    uint32_t a_off[2], a_swz[2];
    #pragma unroll
    for (int mt = 0; mt < 2; mt++) {
        int r = wm * 32 + mt * 16 + (lane & 15);
        a_off[mt] = (uint32_t)r * 128u;
        a_swz[mt] = (uint32_t)((r ^ (r >> 3)) & 7);
    }
    const uint32_t b_ldm = (uint32_t)((lane & 15) * B_ROW
                         + (wn * 64 + (lane >> 4) * 8) * 2);

    float acc[2][8][4] = {};
    const int NCH = K / 64;

    // ---- prologue ----
    {
        float4 bv[8];
        #pragma unroll
        for (int j = 0; j < 8; j++) {
            int idx = tid + j * 512;
            bv[j] = *reinterpret_cast<const float4*>(
                wsrc + (size_t)(idx >> 6) * NTOT + (idx & 63) * 4);
        }
        #pragma unroll
        for (int j = 0; j < 8; j++) {
            int idx = tid + j * 512;
            sts64(bbase + (uint32_t)((idx >> 6) * B_ROW + (idx & 63) * 8),
                  pack_h2(bv[j].x, bv[j].y), pack_h2(bv[j].z, bv[j].w));
        }
    }
    #pragma unroll
    for (int s = 0; s < 3; s++) {
        if (isA) {
            const __half* sp = asrc + s * 64;
            const uint32_t stp = sbase + s * A_STAGE;
            #pragma unroll
            for (int u = 0; u < 8; u++)
                CP16(stp + adof + (((u ^ aswz) & 7) << 4), sp + u * 8);
        }
        CP_COMMIT();
    }

    for (int c = 0; c < NCH; c++) {
        if      (c + 3 <= NCH) { CP_WAIT(2); }
        else if (c + 2 <= NCH) { CP_WAIT(1); }
        else                   { CP_WAIT(0); }
        __syncthreads();   // single barrier per chunk

        // A prefetch chunk c+3
        if (c + 3 < NCH) {
            const uint32_t st2 = sbase + ((c + 3) & 3) * A_STAGE;
            if (isA) {
                const __half* s2 = asrc + (c + 3) * 64;
                #pragma unroll
                for (int u = 0; u < 8; u++)
                    CP16(st2 + adof + (((u ^ aswz) & 7) << 4), s2 + u * 8);
            }
            CP_COMMIT();
        }

        // B prefetch chunk c+1 into registers (STS after MMA)
        float4 bv[8];
        if (c + 1 < NCH) {
            const float* w2 = wsrc + (size_t)(c + 1) * 64 * NTOT;
            #pragma unroll
            for (int j = 0; j < 8; j++) {
                int idx = tid + j * 512;
                bv[j] = *reinterpret_cast<const float4*>(
                    w2 + (size_t)(idx >> 6) * NTOT + (idx & 63) * 4);
            }
        }

        // ---- MMA on chunk c: A stage c&3, B stage c&1 ----
        const uint32_t ast = sbase + (c & 3) * A_STAGE;
        const uint32_t bst = bbase + (c & 1) * B_STAGE;
        #pragma unroll
        for (int ks = 0; ks < 4; ks++) {
            const uint32_t u = ks * 2 + uh;
            uint32_t a[2][4];
            #pragma unroll
            for (int mt = 0; mt < 2; mt++)
                ldm_x4(a[mt], ast + a_off[mt] + (((u ^ a_swz[mt]) & 7) << 4));
            #pragma unroll
            for (int ng = 0; ng < 4; ng++) {
                uint32_t b[4];
                ldm_x4_t(b, bst + b_ldm + ks * 16 * B_ROW + ng * 32);
                #pragma unroll
                for (int mt = 0; mt < 2; mt++) {
                    mma_f16(acc[mt][ng * 2 + 0], a[mt], b[0], b[1]);
                    mma_f16(acc[mt][ng * 2 + 1], a[mt], b[2], b[3]);
                }
            }
        }

        // STS B chunk c+1 into stage (c+1)&1
        if (c + 1 < NCH) {
            const uint32_t bs2 = bbase + ((c + 1) & 1) * B_STAGE;
            #pragma unroll
            for (int j = 0; j < 8; j++) {
                int idx = tid + j * 512;
                sts64(bs2 + (uint32_t)((idx >> 6) * B_ROW + (idx & 63) * 8),
                      pack_h2(bv[j].x, bv[j].y), pack_h2(bv[j].z, bv[j].w));
            }
        }
    }

    // ---- Epilogue ----
    const float* bp = bias + (size_t)m * NTOT + n0;
    #pragma unroll
    for (int mt = 0; mt < 2; mt++) {
        #pragma unroll
        for (int half = 0; half < 2; half++) {
            int rloc = wm * 32 + mt * 16 + (lane >> 2) + half * 8;
            int r = row0 + rloc;
            if (r >= cnt) continue;
            if (LAYER1) {
                __half* hp = g_hq + (size_t)(goff + r) * NTOT + n0;
                #pragma unroll
                for (int nt = 0; nt < 8; nt++) {
                    int col = wn * 64 + nt * 8 + (lane & 3) * 2;
                    float v0 = gelu_tanh(acc[mt][nt][half * 2 + 0] + bp[col]);
                    float v1 = gelu_tanh(acc[mt][nt][half * 2 + 1] + bp[col + 1]);
                    *reinterpret_cast<uint32_t*>(hp + col) = pack_h2(v0, v1);
                }
            } else {
                float* cp = Cout + (size_t)g_order[goff + r] * NTOT + n0;
                #pragma unroll
                for (int nt = 0; nt < 8; nt++) {
                    int col = wn * 64 + nt * 8 + (lane & 3) * 2;
                    float2 v;
                    v.x = acc[mt][nt][half * 2 + 0] + bp[col];
                    v.y = acc[mt][nt][half * 2 + 1] + bp[col + 1];
                    *reinterpret_cast<float2*>(cp + col) = v;
                }
            }
        }
    }
}

// ---------------------------------------------------------------------------
extern "C" void kernel_launch(void* const* d_in, const int* in_sizes, int n_in,
                              void* d_out, int out_size)
{
    const float* x     = (const float*)d_in[0];
    const void*  route = d_in[1];
    const float* W1    = (const float*)d_in[2];
    const float* b1    = (const float*)d_in[3];
    const float* W2    = (const float*)d_in[4];
    const float* b2    = (const float*)d_in[5];
    float*       out   = (float*)d_out;

    __half *xq, *hq;
    cudaGetSymbolAddress((void**)&xq, g_xq);
    cudaGetSymbolAddress((void**)&hq, g_hq);

    cudaFuncSetAttribute(moe_gemm<DIN, DHID, true>,
                         cudaFuncAttributeMaxDynamicSharedMemorySize, SMEM_DYN);
    cudaFuncSetAttribute(moe_gemm<DHID, DOUT, false>,
                         cudaFuncAttributeMaxDynamicSharedMemorySize, SMEM_DYN);

    route_kernel<<<1, 1024>>>((const int*)route);
    quant_x_kernel<<<(BTOK * DIN / 8) / 256, 256>>>(x);

    {   // Layer 1: g_hq = fp16(gelu(x @ W1[m] + b1[m])), grouped by expert
        dim3 g(DHID / 256, MAXTILES, 1);
        moe_gemm<DIN, DHID, true><<<g, 512, SMEM_DYN>>>(xq, W1, b1, nullptr);
    }
    {   // Layer 2: out[tok] = h @ W2[m] + b2[m]
        dim3 g(DOUT / 256, MAXTILES, 1);
        moe_gemm<DHID, DOUT, false><<<g, 512, SMEM_DYN>>>(hq, W2, b2, out);
    }
}